// round 8
// baseline (speedup 1.0000x reference)
#include <cuda_runtime.h>
#include <cstdint>

// Problem constants
#define BATCH 64
#define TT    1000
#define NINP  64
#define HID   512
#define NACT  2

// Recurrence decomposition
#define CNC  8                    // CTAs per cluster (W_hh split by column)
#define NB   4                    // batches per cluster
#define JPC  64                   // HID / CNC columns per CTA
#define NCLUSTER (BATCH / NB)     // 16 clusters -> 128 CTAs
#define NTHR 512

// d_out layout: [out | hn_last | rnn_out]
#define HN_OFF  (BATCH * TT * NACT)
#define RNN_OFF (HN_OFF + BATCH * HID)

typedef unsigned long long u64;
typedef unsigned int u32;

// ---- packed f32x2 helpers ----
__device__ __forceinline__ u64 pk(float lo, float hi) {
    u64 r; asm("mov.b64 %0, {%1, %2};" : "=l"(r) : "f"(lo), "f"(hi)); return r;
}
__device__ __forceinline__ void upk(u64 v, float& lo, float& hi) {
    asm("mov.b64 {%0, %1}, %2;" : "=f"(lo), "=f"(hi) : "l"(v));
}
__device__ __forceinline__ u64 f2fma(u64 a, u64 b, u64 c) {
    u64 d; asm("fma.rn.f32x2 %0, %1, %2, %3;" : "=l"(d) : "l"(a), "l"(b), "l"(c));
    return d;
}

// ---- mbarrier helpers ----
#define MBINIT(addr, cnt) \
    asm volatile("mbarrier.init.shared.b64 [%0], %1;" :: "r"(addr), "r"(cnt) : "memory")
#define MB_ARRIVE(addr) \
    asm volatile("mbarrier.arrive.release.cta.shared::cta.b64 _, [%0];" :: "r"(addr) : "memory")
#define MB_ARRIVE_EXPECT(addr, tx) \
    asm volatile("mbarrier.arrive.expect_tx.release.cta.shared::cta.b64 _, [%0], %1;" :: "r"(addr), "r"(tx) : "memory")
#define WAITC(addr, ph) \
    asm volatile("{\n\t.reg .pred P;\n\tWL%=:\n\t" \
                 "mbarrier.try_wait.parity.acquire.cta.shared::cta.b64 P, [%0], %1, 0x989680;\n\t" \
                 "@!P bra WL%=;\n\t}" :: "r"(addr), "r"(ph) : "memory")

// ---------------------------------------------------------------------------
__global__ void k_nop() {}   // keeps ncu capture index on k_rnn

// ---------------------------------------------------------------------------
// Kernel A: inp_proj = inp @ W_ih  (into rnn region, consumed in place)
// ---------------------------------------------------------------------------
__global__ void __launch_bounds__(512, 1) k_inproj(
    const float* __restrict__ inp, const float* __restrict__ W_ih,
    float* __restrict__ rnn)
{
    __shared__ alignas(16) float2 xsp[16][NINP];   // [row_pair][k]
    const int row0 = blockIdx.x * 32;
    for (int i = threadIdx.x; i < 32 * NINP; i += 512) {
        const int r = i >> 6, k = i & 63;
        ((float*)&xsp[r >> 1][k])[r & 1] = inp[(size_t)(row0 + r) * NINP + k];
    }
    __syncthreads();

    const int j = threadIdx.x;
    u64 acc[16];
#pragma unroll
    for (int r2 = 0; r2 < 16; r2++) acc[r2] = 0ull;

#pragma unroll 8
    for (int k = 0; k < NINP; k += 2) {
        const float wa = W_ih[k * HID + j];
        const float wb = W_ih[(k + 1) * HID + j];
        const u64 w0 = pk(wa, wa), w1 = pk(wb, wb);
#pragma unroll
        for (int r2 = 0; r2 < 16; r2++) {
            const ulonglong2 hv = *reinterpret_cast<const ulonglong2*>(&xsp[r2][k]);
            acc[r2] = f2fma(hv.x, w0, acc[r2]);
            acc[r2] = f2fma(hv.y, w1, acc[r2]);
        }
    }
#pragma unroll
    for (int r2 = 0; r2 < 16; r2++) {
        float lo, hi; upk(acc[r2], lo, hi);
        rnn[(size_t)(row0 + 2 * r2) * HID + j]     = lo;
        rnn[(size_t)(row0 + 2 * r2 + 1) * HID + j] = hi;
    }
}

// ---------------------------------------------------------------------------
// Kernel B: persistent clustered recurrence, 4 phase-staggered batch phases.
// h_perm[buf][rb*256 + b*64 + jj], logical k = rb*64 + jj.
// Per-(buf,batch) full barriers: count=64 local epi arrives + 1792B remote tx.
// Exchange: each of 64 epi threads st.asyncs its value to 7 peers.
// ---------------------------------------------------------------------------
__global__ void __cluster_dims__(CNC, 1, 1) __launch_bounds__(NTHR, 1)
k_rnn(const float* __restrict__ hn, const float* __restrict__ W_hh,
      float* __restrict__ rnn, float* __restrict__ hn_last)
{
    __shared__ alignas(16) float h_perm[2][CNC * NB * JPC];  // 2 x 8KB
    __shared__ alignas(16) float red[NB][CNC][JPC];          // 8KB (per batch)
    __shared__ alignas(8)  u64   mb[2][NB];                  // full[buf][batch]

    u32 rank; asm("mov.u32 %0, %%cluster_ctarank;" : "=r"(rank));
    const int rank_i = (int)rank;
    const int cid    = blockIdx.x / CNC;
    const int b_base = cid * NB;

    const int tid = threadIdx.x;
    const int j   = tid & 63;     // column within CTA
    const int kg  = tid >> 6;     // source rank-block 0..7 (64 k each)
    const int col = rank_i * JPC + j;

    // epi duty: batch eb handled by tid in [128*eb, 128*eb+64)
    const int  eb     = tid >> 7;
    const bool is_epi = ((tid & 127) < 64);

    // Weights: thread (kg, j) holds k in [kg*64, kg*64+64) for column col
    u64 w2[32];
#pragma unroll
    for (int q = 0; q < 32; q++) {
        const int k = kg * 64 + 2 * q;
        w2[q] = pk(W_hh[(size_t)k * HID + col], W_hh[(size_t)(k + 1) * HID + col]);
    }

    // Prefill h_perm[0] with h0 (permuted)
    for (int i = tid; i < CNC * NB * JPC; i += NTHR) {
        const int r = i >> 8, b = (i >> 6) & 3, jj = i & 63;
        h_perm[0][i] = hn[(size_t)(b_base + b) * HID + r * JPC + jj];
    }

    const u32 mb_base = (u32)__cvta_generic_to_shared(&mb[0][0]);
    if (tid < 2 * NB) MBINIT(mb_base + (u32)tid * 8, 64);
    __syncthreads();
    asm volatile("barrier.cluster.arrive.aligned;\n\t"
                 "barrier.cluster.wait.aligned;" ::: "memory");

    const u32 hl = (u32)__cvta_generic_to_shared(&h_perm[0][0]);
    u32 rh[CNC], rm[CNC];
#pragma unroll
    for (int p = 0; p < CNC; p++) {
        asm("mapa.shared::cluster.u32 %0, %1, %2;" : "=r"(rh[p]) : "r"(hl), "r"(p));
        asm("mapa.shared::cluster.u32 %0, %1, %2;" : "=r"(rm[p]) : "r"(mb_base), "r"(p));
    }

    // epi thread's gmem pointers (batch b_base+eb, column col)
    const int egb = b_base + eb;
    float* xptr = (float*)(rnn + (size_t)egb * TT * HID + col);
    float xv = is_epi ? __ldg(xptr) : 0.f;

#pragma unroll 1
    for (int t = 0; t < TT; t++) {
        const int cur = t & 1, nxt = cur ^ 1, m = t >> 1;
        const u32 wp = (u32)((cur ? m : (m + 1)) & 1);
        const bool last = (t == TT - 1);

#pragma unroll
        for (int b = 0; b < NB; b++) {
            if (t > 0) WAITC(mb_base + (u32)(cur * NB + b) * 8, wp);

            // FMA: our kg block (64 k) for batch b
            const ulonglong2* hp =
                (const ulonglong2*)&h_perm[cur][kg * 256 + b * 64];
            u64 a = 0ull;
#pragma unroll
            for (int q = 0; q < 16; q++) {
                const ulonglong2 v = hp[q];
                a = f2fma(v.x, w2[2 * q], a);
                a = f2fma(v.y, w2[2 * q + 1], a);
            }
            float lo, hi; upk(a, lo, hi);
            red[b][kg][j] = lo + hi;

            if (is_epi && eb == b) {
                asm volatile("bar.sync %0, %1;" :: "r"(b + 1), "r"(NTHR) : "memory");
                float v = xv;
#pragma unroll
                for (int r = 0; r < CNC; r++) v += red[b][r][j];
                const float hval = 1.f / (1.f + __expf(-v));

                if (!last) {
                    // stage locally (our own block of next buffer)
                    h_perm[nxt][rank_i * 256 + b * 64 + j] = hval;
                    // local release-arrive (leader also posts expect_tx 1792B)
                    const u32 fb = mb_base + (u32)(nxt * NB + b) * 8;
                    if ((tid & 127) == 0) { MB_ARRIVE_EXPECT(fb, (CNC - 1) * JPC * 4); }
                    else                  { MB_ARRIVE(fb); }
                    // send our value to all 7 peers (tx onto their full[nxt][b])
                    const u32 voff = (u32)((nxt * (CNC * NB * JPC) +
                                            rank_i * 256 + b * 64 + j) * 4);
                    const u32 boff = (u32)((nxt * NB + b) * 8);
#pragma unroll
                    for (int p = 0; p < CNC; p++) {
                        if (p == rank_i) continue;
                        asm volatile(
                            "st.async.shared::cluster.mbarrier::complete_tx::bytes.b32 "
                            "[%0], %1, [%2];"
                            :: "r"(rh[p] + voff), "f"(hval), "r"(rm[p] + boff)
                            : "memory");
                    }
                    // off critical path: rnn_out store + x prefetch
                    xptr[(size_t)t * HID] = hval;
                    xv = __ldg(xptr + (size_t)(t + 1) * HID);
                } else {
                    xptr[(size_t)t * HID] = hval;
                    hn_last[(size_t)egb * HID + col] = hval;
                }
            } else {
                asm volatile("bar.arrive %0, %1;" :: "r"(b + 1), "r"(NTHR) : "memory");
            }
        }
    }
}

// ---------------------------------------------------------------------------
// Kernel C: out = sigmoid(rnn_out @ W_fc + b_fc). One warp per (b,t) row.
// ---------------------------------------------------------------------------
__global__ void __launch_bounds__(256, 8) k_fc(
    const float* __restrict__ rnn, const float* __restrict__ W_fc,
    const float* __restrict__ b_fc, float* __restrict__ out)
{
    __shared__ float wfc[HID * NACT];
    for (int i = threadIdx.x; i < HID * NACT; i += 256) wfc[i] = W_fc[i];
    __syncthreads();

    const int warp = threadIdx.x >> 5, lane = threadIdx.x & 31;
    const size_t row = (size_t)blockIdx.x * 8 + warp;
    const float4* rp = reinterpret_cast<const float4*>(rnn + row * HID);

    float a0 = 0.f, a1 = 0.f;
#pragma unroll
    for (int i = 0; i < 4; i++) {
        const float4 vv = rp[lane + 32 * i];
        const int k = (lane + 32 * i) * 4;
        a0 = fmaf(vv.x, wfc[(k + 0) * 2 + 0], a0);
        a1 = fmaf(vv.x, wfc[(k + 0) * 2 + 1], a1);
        a0 = fmaf(vv.y, wfc[(k + 1) * 2 + 0], a0);
        a1 = fmaf(vv.y, wfc[(k + 1) * 2 + 1], a1);
        a0 = fmaf(vv.z, wfc[(k + 2) * 2 + 0], a0);
        a1 = fmaf(vv.z, wfc[(k + 2) * 2 + 1], a1);
        a0 = fmaf(vv.w, wfc[(k + 3) * 2 + 0], a0);
        a1 = fmaf(vv.w, wfc[(k + 3) * 2 + 1], a1);
    }
#pragma unroll
    for (int off = 16; off > 0; off >>= 1) {
        a0 += __shfl_xor_sync(0xffffffffu, a0, off);
        a1 += __shfl_xor_sync(0xffffffffu, a1, off);
    }
    if (lane == 0) {
        out[row * NACT + 0] = 1.f / (1.f + __expf(-(a0 + b_fc[0])));
        out[row * NACT + 1] = 1.f / (1.f + __expf(-(a1 + b_fc[1])));
    }
}

// ---------------------------------------------------------------------------
extern "C" void kernel_launch(void* const* d_in, const int* in_sizes, int n_in,
                              void* d_out, int out_size)
{
    const float* inp  = (const float*)d_in[0];
    const float* hn   = (const float*)d_in[1];
    const float* W_hh = (const float*)d_in[2];
    const float* W_ih = (const float*)d_in[3];
    const float* W_fc = (const float*)d_in[4];
    const float* b_fc = (const float*)d_in[5];

    float* out = (float*)d_out;
    float* hnl = out + HN_OFF;
    float* rnn = out + RNN_OFF;

    k_inproj<<<(BATCH * TT) / 32, 512>>>(inp, W_ih, rnn);
    k_nop<<<1, 32>>>();
    k_nop<<<1, 32>>>();
    k_rnn<<<NCLUSTER * CNC, NTHR>>>(hn, W_hh, rnn, hnl);
    k_fc<<<(BATCH * TT) / 8, 256>>>(rnn, W_fc, b_fc, out);
}

// round 9
// speedup vs baseline: 1.9068x; 1.9068x over previous
#include <cuda_runtime.h>
#include <cstdint>

// Problem constants
#define BATCH 64
#define TT    1000
#define NINP  64
#define HID   512
#define NACT  2

// Recurrence decomposition: 16 groups x 8 CTAs (no HW clusters needed)
#define GNC  8                    // CTAs per group (W_hh split by column)
#define NB   4                    // batches per group
#define JPC  64                   // HID / GNC columns per CTA
#define NGROUP (BATCH / NB)       // 16 groups -> 128 CTAs
#define NTHR 512

// d_out layout: [out | hn_last | rnn_out]
#define HN_OFF  (BATCH * TT * NACT)
#define RNN_OFF (HN_OFF + BATCH * HID)

typedef unsigned long long u64;
typedef unsigned int u32;

// L2 exchange scratch: [cta 128][buf 2][src 8][j 64][b 4] floats = 2MB
#define EXCH_FLOATS (128 * 2 * 8 * 64 * 4)
__device__ __align__(16) float g_exch[EXCH_FLOATS];

__device__ __forceinline__ int exch_idx(int cta, int buf, int src, int j) {
    return (((cta * 2 + buf) * 8 + src) * 64 + j) * 4;
}

// ---- packed f32x2 helpers ----
__device__ __forceinline__ u64 pk(float lo, float hi) {
    u64 r; asm("mov.b64 %0, {%1, %2};" : "=l"(r) : "f"(lo), "f"(hi)); return r;
}
__device__ __forceinline__ void upk(u64 v, float& lo, float& hi) {
    asm("mov.b64 {%0, %1}, %2;" : "=f"(lo), "=f"(hi) : "l"(v));
}
__device__ __forceinline__ u64 f2fma(u64 a, u64 b, u64 c) {
    u64 d; asm("fma.rn.f32x2 %0, %1, %2, %3;" : "=l"(d) : "l"(a), "l"(b), "l"(c));
    return d;
}

// ---------------------------------------------------------------------------
__global__ void k_clear() {   // reset exchange scratch to invalid sentinel
    float4* p = reinterpret_cast<float4*>(g_exch);
    const int n4 = EXCH_FLOATS / 4;
    const float4 s = make_float4(-1.f, -1.f, -1.f, -1.f);
    for (int i = blockIdx.x * blockDim.x + threadIdx.x; i < n4;
         i += gridDim.x * blockDim.x)
        p[i] = s;
}

__global__ void k_nop() {}    // keeps ncu capture index aligned on k_rnn

// ---------------------------------------------------------------------------
// Kernel A: inp_proj = inp @ W_ih  (into rnn region, consumed in place)
// ---------------------------------------------------------------------------
__global__ void __launch_bounds__(512, 1) k_inproj(
    const float* __restrict__ inp, const float* __restrict__ W_ih,
    float* __restrict__ rnn)
{
    __shared__ alignas(16) float2 xsp[16][NINP];   // [row_pair][k]
    const int row0 = blockIdx.x * 32;
    for (int i = threadIdx.x; i < 32 * NINP; i += 512) {
        const int r = i >> 6, k = i & 63;
        ((float*)&xsp[r >> 1][k])[r & 1] = inp[(size_t)(row0 + r) * NINP + k];
    }
    __syncthreads();

    const int j = threadIdx.x;
    u64 acc[16];
#pragma unroll
    for (int r2 = 0; r2 < 16; r2++) acc[r2] = 0ull;

#pragma unroll 8
    for (int k = 0; k < NINP; k += 2) {
        const float wa = W_ih[k * HID + j];
        const float wb = W_ih[(k + 1) * HID + j];
        const u64 w0 = pk(wa, wa), w1 = pk(wb, wb);
#pragma unroll
        for (int r2 = 0; r2 < 16; r2++) {
            const ulonglong2 hv = *reinterpret_cast<const ulonglong2*>(&xsp[r2][k]);
            acc[r2] = f2fma(hv.x, w0, acc[r2]);
            acc[r2] = f2fma(hv.y, w1, acc[r2]);
        }
    }
#pragma unroll
    for (int r2 = 0; r2 < 16; r2++) {
        float lo, hi; upk(acc[r2], lo, hi);
        rnn[(size_t)(row0 + 2 * r2) * HID + j]     = lo;
        rnn[(size_t)(row0 + 2 * r2 + 1) * HID + j] = hi;
    }
}

// ---------------------------------------------------------------------------
// Kernel B: persistent recurrence, L2-exchange with tagged self-validating
// values. h_perm[buf][src*256 + b*64 + kk], logical k = src*64 + kk.
// Poll duty: thread (kg != rank, j) spins on ITS float4 (h of 4 batches for
// word j of source block kg). Epilogue duty: group kg == rank.
// Value encoding: v = h + 2*((t)&7); valid iff (v - 2*tag) in [0,1].
// ---------------------------------------------------------------------------
__global__ void __launch_bounds__(NTHR, 1)
k_rnn(const float* __restrict__ hn, const float* __restrict__ W_hh,
      float* __restrict__ rnn, float* __restrict__ hn_last)
{
    __shared__ alignas(16) float h_perm[2][GNC * NB * JPC];  // 2 x 8KB
    __shared__ alignas(16) float red[2][GNC][NB][JPC];       // 2 x 8KB

    const int me     = blockIdx.x;
    const int group  = me >> 3;
    const int rank_i = me & 7;
    const int b_base = group * NB;

    const int tid = threadIdx.x;
    const int j   = tid & 63;     // column / word index
    const int kg  = tid >> 6;     // source block 0..7 (64 k each)
    const int col = rank_i * JPC + j;
    const bool is_epi = (kg == rank_i);

    // Weights: thread (kg, j) holds k in [kg*64, kg*64+64) for column col
    u64 w2[32];
#pragma unroll
    for (int q = 0; q < 32; q++) {
        const int k = kg * 64 + 2 * q;
        w2[q] = pk(W_hh[(size_t)k * HID + col], W_hh[(size_t)(k + 1) * HID + col]);
    }

    // Prefill h_perm[0] with h0 (permuted): block r holds k in [r*64, r*64+64)
    for (int i = tid; i < GNC * NB * JPC; i += NTHR) {
        const int r = i >> 8, b = (i >> 6) & 3, kk = i & 63;
        h_perm[0][i] = hn[(size_t)(b_base + b) * HID + r * JPC + kk];
    }
    __syncthreads();

    // epi thread state: x pointers + prefetched x values (4 batches)
    float* xp[NB];
    float xv[NB];
#pragma unroll
    for (int b = 0; b < NB; b++) {
        xp[b] = (float*)(rnn + (size_t)(b_base + b) * TT * HID + col);
        xv[b] = is_epi ? __ldg(xp[b]) : 0.f;
    }

#pragma unroll 1
    for (int t = 0; t < TT; t++) {
        const int cur = t & 1, nxt = cur ^ 1, par = t & 1;

        // ---- Phase A: arrival (poll our word of block kg) ----
        if (!is_epi && t > 0) {
            const float lo = 2.0f * (float)(t & 7);
            const float* src = g_exch + exch_idx(me, cur, kg, j);
            float x0, x1, x2, x3;
            while (true) {
                asm volatile("ld.volatile.global.v4.f32 {%0,%1,%2,%3}, [%4];"
                             : "=f"(x0), "=f"(x1), "=f"(x2), "=f"(x3)
                             : "l"(src));
                x0 -= lo; x1 -= lo; x2 -= lo; x3 -= lo;
                if (x0 >= 0.f && x0 <= 1.f && x1 >= 0.f && x1 <= 1.f &&
                    x2 >= 0.f && x2 <= 1.f && x3 >= 0.f && x3 <= 1.f) break;
            }
            float* hb = &h_perm[cur][kg * 256];
            hb[0 * 64 + j] = x0;
            hb[1 * 64 + j] = x1;
            hb[2 * 64 + j] = x2;
            hb[3 * 64 + j] = x3;
        }
        // group rendezvous: all 64 words of block kg staged (epi block was
        // staged locally by the epilogue of step t-1)
        asm volatile("bar.sync %0, 64;" :: "r"(kg + 1) : "memory");

        // ---- Phase B: FMA over our block for 4 batches ----
        const float* hc = &h_perm[cur][kg * 256];
        const ulonglong2* hp0 = (const ulonglong2*)(hc);
        const ulonglong2* hp1 = (const ulonglong2*)(hc + 64);
        const ulonglong2* hp2 = (const ulonglong2*)(hc + 128);
        const ulonglong2* hp3 = (const ulonglong2*)(hc + 192);
        u64 a0 = 0ull, a1 = 0ull, a2 = 0ull, a3 = 0ull;
#pragma unroll
        for (int q = 0; q < 16; q++) {
            const ulonglong2 v0 = hp0[q];
            a0 = f2fma(v0.x, w2[2 * q], a0); a0 = f2fma(v0.y, w2[2 * q + 1], a0);
            const ulonglong2 v1 = hp1[q];
            a1 = f2fma(v1.x, w2[2 * q], a1); a1 = f2fma(v1.y, w2[2 * q + 1], a1);
            const ulonglong2 v2 = hp2[q];
            a2 = f2fma(v2.x, w2[2 * q], a2); a2 = f2fma(v2.y, w2[2 * q + 1], a2);
            const ulonglong2 v3 = hp3[q];
            a3 = f2fma(v3.x, w2[2 * q], a3); a3 = f2fma(v3.y, w2[2 * q + 1], a3);
        }
        {
            float lo, hi;
            upk(a0, lo, hi); red[par][kg][0][j] = lo + hi;
            upk(a1, lo, hi); red[par][kg][1][j] = lo + hi;
            upk(a2, lo, hi); red[par][kg][2][j] = lo + hi;
            upk(a3, lo, hi); red[par][kg][3][j] = lo + hi;
        }
        __syncthreads();   // red[par] complete across all groups

        // ---- Phase C: epilogue (group rank only) ----
        if (is_epi) {
            float h4[NB];
#pragma unroll
            for (int b = 0; b < NB; b++) {
                float v = xv[b];
#pragma unroll
                for (int r = 0; r < GNC; r++) v += red[par][r][b][j];
                h4[b] = 1.f / (1.f + __expf(-v));
            }
            if (t < TT - 1) {
                // stage our block locally for next step
                float* hb = &h_perm[nxt][rank_i * 256];
                hb[0 * 64 + j] = h4[0];
                hb[1 * 64 + j] = h4[1];
                hb[2 * 64 + j] = h4[2];
                hb[3 * 64 + j] = h4[3];
                // tagged send to 7 peers
                const float tagf = 2.0f * (float)((t + 1) & 7);
                const float y0 = h4[0] + tagf, y1 = h4[1] + tagf;
                const float y2 = h4[2] + tagf, y3 = h4[3] + tagf;
#pragma unroll
                for (int p = 0; p < GNC; p++) {
                    if (p == rank_i) continue;
                    float* dst = g_exch + exch_idx((group << 3) | p, nxt, rank_i, j);
                    asm volatile("st.volatile.global.v4.f32 [%0], {%1,%2,%3,%4};"
                                 :: "l"(dst), "f"(y0), "f"(y1), "f"(y2), "f"(y3)
                                 : "memory");
                }
                // off critical path: outputs + next x prefetch
#pragma unroll
                for (int b = 0; b < NB; b++) {
                    xp[b][(size_t)t * HID] = h4[b];
                    xv[b] = __ldg(xp[b] + (size_t)(t + 1) * HID);
                }
            } else {
#pragma unroll
                for (int b = 0; b < NB; b++) {
                    xp[b][(size_t)t * HID] = h4[b];
                    hn_last[(size_t)(b_base + b) * HID + col] = h4[b];
                }
            }
        }
    }
}

// ---------------------------------------------------------------------------
// Kernel C: out = sigmoid(rnn_out @ W_fc + b_fc). One warp per (b,t) row.
// ---------------------------------------------------------------------------
__global__ void __launch_bounds__(256, 8) k_fc(
    const float* __restrict__ rnn, const float* __restrict__ W_fc,
    const float* __restrict__ b_fc, float* __restrict__ out)
{
    __shared__ float wfc[HID * NACT];
    for (int i = threadIdx.x; i < HID * NACT; i += 256) wfc[i] = W_fc[i];
    __syncthreads();

    const int warp = threadIdx.x >> 5, lane = threadIdx.x & 31;
    const size_t row = (size_t)blockIdx.x * 8 + warp;
    const float4* rp = reinterpret_cast<const float4*>(rnn + row * HID);

    float a0 = 0.f, a1 = 0.f;
#pragma unroll
    for (int i = 0; i < 4; i++) {
        const float4 vv = rp[lane + 32 * i];
        const int k = (lane + 32 * i) * 4;
        a0 = fmaf(vv.x, wfc[(k + 0) * 2 + 0], a0);
        a1 = fmaf(vv.x, wfc[(k + 0) * 2 + 1], a1);
        a0 = fmaf(vv.y, wfc[(k + 1) * 2 + 0], a0);
        a1 = fmaf(vv.y, wfc[(k + 1) * 2 + 1], a1);
        a0 = fmaf(vv.z, wfc[(k + 2) * 2 + 0], a0);
        a1 = fmaf(vv.z, wfc[(k + 2) * 2 + 1], a1);
        a0 = fmaf(vv.w, wfc[(k + 3) * 2 + 0], a0);
        a1 = fmaf(vv.w, wfc[(k + 3) * 2 + 1], a1);
    }
#pragma unroll
    for (int off = 16; off > 0; off >>= 1) {
        a0 += __shfl_xor_sync(0xffffffffu, a0, off);
        a1 += __shfl_xor_sync(0xffffffffu, a1, off);
    }
    if (lane == 0) {
        out[row * NACT + 0] = 1.f / (1.f + __expf(-(a0 + b_fc[0])));
        out[row * NACT + 1] = 1.f / (1.f + __expf(-(a1 + b_fc[1])));
    }
}

// ---------------------------------------------------------------------------
extern "C" void kernel_launch(void* const* d_in, const int* in_sizes, int n_in,
                              void* d_out, int out_size)
{
    const float* inp  = (const float*)d_in[0];
    const float* hn   = (const float*)d_in[1];
    const float* W_hh = (const float*)d_in[2];
    const float* W_ih = (const float*)d_in[3];
    const float* W_fc = (const float*)d_in[4];
    const float* b_fc = (const float*)d_in[5];

    float* out = (float*)d_out;
    float* hnl = out + HN_OFF;
    float* rnn = out + RNN_OFF;

    k_clear<<<128, 256>>>();                              // reset exchange tags
    k_inproj<<<(BATCH * TT) / 32, 512>>>(inp, W_ih, rnn);
    k_nop<<<1, 32>>>();                                   // ncu index alignment
    k_rnn<<<NGROUP * GNC, NTHR>>>(hn, W_hh, rnn, hnl);
    k_fc<<<(BATCH * TT) / 8, 256>>>(rnn, W_fc, b_fc, out);
}

// round 10
// speedup vs baseline: 1.9373x; 1.0160x over previous
#include <cuda_runtime.h>
#include <cstdint>

// Problem constants
#define BATCH 64
#define TT    1000
#define NINP  64
#define HID   512
#define NACT  2

// Recurrence decomposition: 16 groups x 8 CTAs (no HW clusters needed)
#define GNC  8                    // CTAs per group (W_hh split by column)
#define NB   4                    // batches per group
#define JPC  64                   // HID / GNC columns per CTA
#define NGROUP (BATCH / NB)       // 16 groups -> 128 CTAs
#define NTHR 512

// d_out layout: [out | hn_last | rnn_out]
#define HN_OFF  (BATCH * TT * NACT)
#define RNN_OFF (HN_OFF + BATCH * HID)

typedef unsigned long long u64;
typedef unsigned int u32;

// L2 exchange scratch, ONE shared slot per (group, buf, src, j):
// [group 16][buf 2][src 8][j 64][b 4] floats = 256KB
#define EXCH_FLOATS (NGROUP * 2 * GNC * JPC * NB)
__device__ __align__(16) float g_exch[EXCH_FLOATS];

__device__ __forceinline__ int exch_idx(int group, int buf, int src, int j) {
    return (((group * 2 + buf) * GNC + src) * JPC + j) * NB;
}

// ---- packed f32x2 helpers ----
__device__ __forceinline__ u64 pk(float lo, float hi) {
    u64 r; asm("mov.b64 %0, {%1, %2};" : "=l"(r) : "f"(lo), "f"(hi)); return r;
}
__device__ __forceinline__ void upk(u64 v, float& lo, float& hi) {
    asm("mov.b64 {%0, %1}, %2;" : "=f"(lo), "=f"(hi) : "l"(v));
}
__device__ __forceinline__ u64 f2fma(u64 a, u64 b, u64 c) {
    u64 d; asm("fma.rn.f32x2 %0, %1, %2, %3;" : "=l"(d) : "l"(a), "l"(b), "l"(c));
    return d;
}

// ---------------------------------------------------------------------------
__global__ void k_clear() {   // reset exchange scratch to invalid sentinel
    float4* p = reinterpret_cast<float4*>(g_exch);
    const int n4 = EXCH_FLOATS / 4;
    const float4 s = make_float4(-1.f, -1.f, -1.f, -1.f);
    for (int i = blockIdx.x * blockDim.x + threadIdx.x; i < n4;
         i += gridDim.x * blockDim.x)
        p[i] = s;
}

__global__ void k_nop() {}    // keeps ncu capture index aligned on k_rnn

// ---------------------------------------------------------------------------
// Kernel A: inp_proj = inp @ W_ih  (into rnn region, consumed in place)
// ---------------------------------------------------------------------------
__global__ void __launch_bounds__(512, 1) k_inproj(
    const float* __restrict__ inp, const float* __restrict__ W_ih,
    float* __restrict__ rnn)
{
    __shared__ alignas(16) float2 xsp[16][NINP];   // [row_pair][k]
    const int row0 = blockIdx.x * 32;
    for (int i = threadIdx.x; i < 32 * NINP; i += 512) {
        const int r = i >> 6, k = i & 63;
        ((float*)&xsp[r >> 1][k])[r & 1] = inp[(size_t)(row0 + r) * NINP + k];
    }
    __syncthreads();

    const int j = threadIdx.x;
    u64 acc[16];
#pragma unroll
    for (int r2 = 0; r2 < 16; r2++) acc[r2] = 0ull;

#pragma unroll 8
    for (int k = 0; k < NINP; k += 2) {
        const float wa = W_ih[k * HID + j];
        const float wb = W_ih[(k + 1) * HID + j];
        const u64 w0 = pk(wa, wa), w1 = pk(wb, wb);
#pragma unroll
        for (int r2 = 0; r2 < 16; r2++) {
            const ulonglong2 hv = *reinterpret_cast<const ulonglong2*>(&xsp[r2][k]);
            acc[r2] = f2fma(hv.x, w0, acc[r2]);
            acc[r2] = f2fma(hv.y, w1, acc[r2]);
        }
    }
#pragma unroll
    for (int r2 = 0; r2 < 16; r2++) {
        float lo, hi; upk(acc[r2], lo, hi);
        rnn[(size_t)(row0 + 2 * r2) * HID + j]     = lo;
        rnn[(size_t)(row0 + 2 * r2 + 1) * HID + j] = hi;
    }
}

// ---------------------------------------------------------------------------
// Kernel B: persistent recurrence, tagged L2 exchange (shared slots), with
// free-flowing k-groups: non-epi groups bar.arrive and run ahead into the
// next step's poll; only the epi group (kg == rank) bar.syncs. Alternating
// named barriers (9/10) by t-parity prevent cross-phase arrival aliasing.
// ---------------------------------------------------------------------------
__global__ void __launch_bounds__(NTHR, 1)
k_rnn(const float* __restrict__ hn, const float* __restrict__ W_hh,
      float* __restrict__ rnn, float* __restrict__ hn_last)
{
    __shared__ alignas(16) float h_perm[2][GNC * NB * JPC];  // 2 x 8KB
    __shared__ alignas(16) float red[2][GNC][NB][JPC];       // 2 x 8KB

    const int me     = blockIdx.x;
    const int group  = me >> 3;
    const int rank_i = me & 7;
    const int b_base = group * NB;

    const int tid = threadIdx.x;
    const int j   = tid & 63;     // column / word index
    const int kg  = tid >> 6;     // source block 0..7 (64 k each)
    const int col = rank_i * JPC + j;
    const bool is_epi = (kg == rank_i);

    // Weights: thread (kg, j) holds k in [kg*64, kg*64+64) for column col
    u64 w2[32];
#pragma unroll
    for (int q = 0; q < 32; q++) {
        const int k = kg * 64 + 2 * q;
        w2[q] = pk(W_hh[(size_t)k * HID + col], W_hh[(size_t)(k + 1) * HID + col]);
    }

    // Prefill h_perm[0] with h0 (permuted): block r holds k in [r*64, r*64+64)
    for (int i = tid; i < GNC * NB * JPC; i += NTHR) {
        const int r = i >> 8, b = (i >> 6) & 3, kk = i & 63;
        h_perm[0][i] = hn[(size_t)(b_base + b) * HID + r * JPC + kk];
    }
    __syncthreads();

    // epi thread state: x pointers + prefetched x values (4 batches)
    float* xp[NB];
    float xv[NB];
#pragma unroll
    for (int b = 0; b < NB; b++) {
        xp[b] = (float*)(rnn + (size_t)(b_base + b) * TT * HID + col);
        xv[b] = is_epi ? __ldg(xp[b]) : 0.f;
    }

#pragma unroll 1
    for (int t = 0; t < TT; t++) {
        const int cur = t & 1, nxt = cur ^ 1, par = t & 1;

        // ---- Phase A: arrival (poll our word of shared slot (group,cur,kg,j))
        if (!is_epi && t > 0) {
            const float lo = 2.0f * (float)(t & 7);
            const float* src = g_exch + exch_idx(group, cur, kg, j);
            float x0, x1, x2, x3;
            while (true) {
                asm volatile("ld.volatile.global.v4.f32 {%0,%1,%2,%3}, [%4];"
                             : "=f"(x0), "=f"(x1), "=f"(x2), "=f"(x3)
                             : "l"(src));
                x0 -= lo; x1 -= lo; x2 -= lo; x3 -= lo;
                if (x0 >= 0.f && x0 <= 1.f && x1 >= 0.f && x1 <= 1.f &&
                    x2 >= 0.f && x2 <= 1.f && x3 >= 0.f && x3 <= 1.f) break;
            }
            float* hb = &h_perm[cur][kg * 256];
            hb[0 * 64 + j] = x0;
            hb[1 * 64 + j] = x1;
            hb[2 * 64 + j] = x2;
            hb[3 * 64 + j] = x3;
        }
        // group rendezvous: all 64 words of block kg staged
        asm volatile("bar.sync %0, 64;" :: "r"(kg + 1) : "memory");

        // ---- Phase B: FMA over our block for 4 batches ----
        const float* hc = &h_perm[cur][kg * 256];
        const ulonglong2* hp0 = (const ulonglong2*)(hc);
        const ulonglong2* hp1 = (const ulonglong2*)(hc + 64);
        const ulonglong2* hp2 = (const ulonglong2*)(hc + 128);
        const ulonglong2* hp3 = (const ulonglong2*)(hc + 192);
        u64 a0 = 0ull, a1 = 0ull, a2 = 0ull, a3 = 0ull;
#pragma unroll
        for (int q = 0; q < 16; q++) {
            const ulonglong2 v0 = hp0[q];
            a0 = f2fma(v0.x, w2[2 * q], a0); a0 = f2fma(v0.y, w2[2 * q + 1], a0);
            const ulonglong2 v1 = hp1[q];
            a1 = f2fma(v1.x, w2[2 * q], a1); a1 = f2fma(v1.y, w2[2 * q + 1], a1);
            const ulonglong2 v2 = hp2[q];
            a2 = f2fma(v2.x, w2[2 * q], a2); a2 = f2fma(v2.y, w2[2 * q + 1], a2);
            const ulonglong2 v3 = hp3[q];
            a3 = f2fma(v3.x, w2[2 * q], a3); a3 = f2fma(v3.y, w2[2 * q + 1], a3);
        }
        {
            float lo, hi;
            upk(a0, lo, hi); red[par][kg][0][j] = lo + hi;
            upk(a1, lo, hi); red[par][kg][1][j] = lo + hi;
            upk(a2, lo, hi); red[par][kg][2][j] = lo + hi;
            upk(a3, lo, hi); red[par][kg][3][j] = lo + hi;
        }

        // ---- producer/consumer rendezvous on red[par] (alternating ids) ----
        if (is_epi) {
            asm volatile("bar.sync %0, %1;" :: "r"(9 + par), "r"(NTHR) : "memory");

            // ---- Phase C: epilogue (epi group only) ----
            float h4[NB];
#pragma unroll
            for (int b = 0; b < NB; b++) {
                float v = xv[b];
#pragma unroll
                for (int r = 0; r < GNC; r++) v += red[par][r][b][j];
                h4[b] = 1.f / (1.f + __expf(-v));
            }
            if (t < TT - 1) {
                // stage our block locally for next step
                float* hb = &h_perm[nxt][rank_i * 256];
                hb[0 * 64 + j] = h4[0];
                hb[1 * 64 + j] = h4[1];
                hb[2 * 64 + j] = h4[2];
                hb[3 * 64 + j] = h4[3];
                // tagged send: ONE shared slot, one STG.128 per thread
                const float tagf = 2.0f * (float)((t + 1) & 7);
                float* dst = g_exch + exch_idx(group, nxt, rank_i, j);
                asm volatile("st.volatile.global.v4.f32 [%0], {%1,%2,%3,%4};"
                             :: "l"(dst),
                                "f"(h4[0] + tagf), "f"(h4[1] + tagf),
                                "f"(h4[2] + tagf), "f"(h4[3] + tagf)
                             : "memory");
                // off critical path: outputs + next x prefetch
#pragma unroll
                for (int b = 0; b < NB; b++) {
                    xp[b][(size_t)t * HID] = h4[b];
                    xv[b] = __ldg(xp[b] + (size_t)(t + 1) * HID);
                }
            } else {
#pragma unroll
                for (int b = 0; b < NB; b++) {
                    xp[b][(size_t)t * HID] = h4[b];
                    hn_last[(size_t)(b_base + b) * HID + col] = h4[b];
                }
            }
        } else {
            // non-epi: release red[par] and flow ahead into next step's poll
            asm volatile("bar.arrive %0, %1;" :: "r"(9 + par), "r"(NTHR) : "memory");
        }
    }
}

// ---------------------------------------------------------------------------
// Kernel C: out = sigmoid(rnn_out @ W_fc + b_fc). One warp per (b,t) row.
// ---------------------------------------------------------------------------
__global__ void __launch_bounds__(256, 8) k_fc(
    const float* __restrict__ rnn, const float* __restrict__ W_fc,
    const float* __restrict__ b_fc, float* __restrict__ out)
{
    __shared__ float wfc[HID * NACT];
    for (int i = threadIdx.x; i < HID * NACT; i += 256) wfc[i] = W_fc[i];
    __syncthreads();

    const int warp = threadIdx.x >> 5, lane = threadIdx.x & 31;
    const size_t row = (size_t)blockIdx.x * 8 + warp;
    const float4* rp = reinterpret_cast<const float4*>(rnn + row * HID);

    float a0 = 0.f, a1 = 0.f;
#pragma unroll
    for (int i = 0; i < 4; i++) {
        const float4 vv = rp[lane + 32 * i];
        const int k = (lane + 32 * i) * 4;
        a0 = fmaf(vv.x, wfc[(k + 0) * 2 + 0], a0);
        a1 = fmaf(vv.x, wfc[(k + 0) * 2 + 1], a1);
        a0 = fmaf(vv.y, wfc[(k + 1) * 2 + 0], a0);
        a1 = fmaf(vv.y, wfc[(k + 1) * 2 + 1], a1);
        a0 = fmaf(vv.z, wfc[(k + 2) * 2 + 0], a0);
        a1 = fmaf(vv.z, wfc[(k + 2) * 2 + 1], a1);
        a0 = fmaf(vv.w, wfc[(k + 3) * 2 + 0], a0);
        a1 = fmaf(vv.w, wfc[(k + 3) * 2 + 1], a1);
    }
#pragma unroll
    for (int off = 16; off > 0; off >>= 1) {
        a0 += __shfl_xor_sync(0xffffffffu, a0, off);
        a1 += __shfl_xor_sync(0xffffffffu, a1, off);
    }
    if (lane == 0) {
        out[row * NACT + 0] = 1.f / (1.f + __expf(-(a0 + b_fc[0])));
        out[row * NACT + 1] = 1.f / (1.f + __expf(-(a1 + b_fc[1])));
    }
}

// ---------------------------------------------------------------------------
extern "C" void kernel_launch(void* const* d_in, const int* in_sizes, int n_in,
                              void* d_out, int out_size)
{
    const float* inp  = (const float*)d_in[0];
    const float* hn   = (const float*)d_in[1];
    const float* W_hh = (const float*)d_in[2];
    const float* W_ih = (const float*)d_in[3];
    const float* W_fc = (const float*)d_in[4];
    const float* b_fc = (const float*)d_in[5];

    float* out = (float*)d_out;
    float* hnl = out + HN_OFF;
    float* rnn = out + RNN_OFF;

    k_clear<<<64, 256>>>();                               // reset exchange tags
    k_inproj<<<(BATCH * TT) / 32, 512>>>(inp, W_ih, rnn);
    k_nop<<<1, 32>>>();                                   // ncu index alignment
    k_rnn<<<NGROUP * GNC, NTHR>>>(hn, W_hh, rnn, hnl);
    k_fc<<<(BATCH * TT) / 8, 256>>>(rnn, W_fc, b_fc, out);
}

// round 11
// speedup vs baseline: 1.9769x; 1.0205x over previous
#include <cuda_runtime.h>
#include <cstdint>

// Problem constants
#define BATCH 64
#define TT    1000
#define NINP  64
#define HID   512
#define NACT  2

// Recurrence decomposition: 16 groups x 8 CTAs (no HW clusters needed)
#define GNC  8                    // CTAs per group (W_hh split by column)
#define NB   4                    // batches per group
#define JPC  64                   // HID / GNC columns per CTA
#define NGROUP (BATCH / NB)       // 16 groups -> 128 CTAs
#define NTHR 512

// d_out layout: [out | hn_last | rnn_out]
#define HN_OFF  (BATCH * TT * NACT)
#define RNN_OFF (HN_OFF + BATCH * HID)

typedef unsigned long long u64;
typedef unsigned int u32;

// L2 exchange scratch, ONE shared slot per (group, buf, src, j):
// [group 16][buf 2][src 8][j 64][b 4] floats = 256KB
#define EXCH_FLOATS (NGROUP * 2 * GNC * JPC * NB)
__device__ __align__(16) float g_exch[EXCH_FLOATS];

__device__ __forceinline__ int exch_idx(int group, int buf, int src, int j) {
    return (((group * 2 + buf) * GNC + src) * JPC + j) * NB;
}

// ---- packed f32x2 helpers ----
__device__ __forceinline__ u64 pk(float lo, float hi) {
    u64 r; asm("mov.b64 %0, {%1, %2};" : "=l"(r) : "f"(lo), "f"(hi)); return r;
}
__device__ __forceinline__ void upk(u64 v, float& lo, float& hi) {
    asm("mov.b64 {%0, %1}, %2;" : "=f"(lo), "=f"(hi) : "l"(v));
}
__device__ __forceinline__ u64 f2fma(u64 a, u64 b, u64 c) {
    u64 d; asm("fma.rn.f32x2 %0, %1, %2, %3;" : "=l"(d) : "l"(a), "l"(b), "l"(c));
    return d;
}

// .cg = L1-bypass, L2-coherent; far cheaper than volatile(STRONG.SYS).
// Word-level tearing is caught by the tag check (stale tag -> retry).
#define POLL_LD(a, b, c, d, src) \
    asm volatile("ld.global.cg.v4.f32 {%0,%1,%2,%3}, [%4];" \
                 : "=f"(a), "=f"(b), "=f"(c), "=f"(d) : "l"(src) : "memory")

// ---------------------------------------------------------------------------
__global__ void k_clear() {   // reset exchange scratch to invalid sentinel
    float4* p = reinterpret_cast<float4*>(g_exch);
    const int n4 = EXCH_FLOATS / 4;
    const float4 s = make_float4(-1.f, -1.f, -1.f, -1.f);
    for (int i = blockIdx.x * blockDim.x + threadIdx.x; i < n4;
         i += gridDim.x * blockDim.x)
        p[i] = s;
}

__global__ void k_nop() {}    // keeps ncu capture index aligned on k_rnn

// ---------------------------------------------------------------------------
// Kernel A: inp_proj = inp @ W_ih  (into rnn region, consumed in place)
// ---------------------------------------------------------------------------
__global__ void __launch_bounds__(512, 1) k_inproj(
    const float* __restrict__ inp, const float* __restrict__ W_ih,
    float* __restrict__ rnn)
{
    __shared__ alignas(16) float2 xsp[16][NINP];   // [row_pair][k]
    const int row0 = blockIdx.x * 32;
    for (int i = threadIdx.x; i < 32 * NINP; i += 512) {
        const int r = i >> 6, k = i & 63;
        ((float*)&xsp[r >> 1][k])[r & 1] = inp[(size_t)(row0 + r) * NINP + k];
    }
    __syncthreads();

    const int j = threadIdx.x;
    u64 acc[16];
#pragma unroll
    for (int r2 = 0; r2 < 16; r2++) acc[r2] = 0ull;

#pragma unroll 8
    for (int k = 0; k < NINP; k += 2) {
        const float wa = W_ih[k * HID + j];
        const float wb = W_ih[(k + 1) * HID + j];
        const u64 w0 = pk(wa, wa), w1 = pk(wb, wb);
#pragma unroll
        for (int r2 = 0; r2 < 16; r2++) {
            const ulonglong2 hv = *reinterpret_cast<const ulonglong2*>(&xsp[r2][k]);
            acc[r2] = f2fma(hv.x, w0, acc[r2]);
            acc[r2] = f2fma(hv.y, w1, acc[r2]);
        }
    }
#pragma unroll
    for (int r2 = 0; r2 < 16; r2++) {
        float lo, hi; upk(acc[r2], lo, hi);
        rnn[(size_t)(row0 + 2 * r2) * HID + j]     = lo;
        rnn[(size_t)(row0 + 2 * r2 + 1) * HID + j] = hi;
    }
}

// ---------------------------------------------------------------------------
// Kernel B: persistent recurrence, tagged L2 exchange (.cg, shared slots),
// free-flowing k-groups, two-in-flight poll, vectorized red4, send-first epi.
// ---------------------------------------------------------------------------
__global__ void __launch_bounds__(NTHR, 1)
k_rnn(const float* __restrict__ hn, const float* __restrict__ W_hh,
      float* __restrict__ rnn, float* __restrict__ hn_last)
{
    __shared__ alignas(16) float h_perm[2][GNC * NB * JPC];  // 2 x 8KB
    __shared__ alignas(16) float red4[2][GNC][JPC][NB];      // 2 x 8KB, b minor

    const int me     = blockIdx.x;
    const int group  = me >> 3;
    const int rank_i = me & 7;
    const int b_base = group * NB;

    const int tid = threadIdx.x;
    const int j   = tid & 63;     // column / word index
    const int kg  = tid >> 6;     // source block 0..7 (64 k each)
    const int col = rank_i * JPC + j;
    const bool is_epi = (kg == rank_i);

    // Weights: thread (kg, j) holds k in [kg*64, kg*64+64) for column col
    u64 w2[32];
#pragma unroll
    for (int q = 0; q < 32; q++) {
        const int k = kg * 64 + 2 * q;
        w2[q] = pk(W_hh[(size_t)k * HID + col], W_hh[(size_t)(k + 1) * HID + col]);
    }

    // Prefill h_perm[0] with h0 (permuted): block r holds k in [r*64, r*64+64)
    for (int i = tid; i < GNC * NB * JPC; i += NTHR) {
        const int r = i >> 8, b = (i >> 6) & 3, kk = i & 63;
        h_perm[0][i] = hn[(size_t)(b_base + b) * HID + r * JPC + kk];
    }
    __syncthreads();

    // epi thread state: x pointers + prefetched x values (4 batches)
    float* xp[NB];
    float xv[NB];
#pragma unroll
    for (int b = 0; b < NB; b++) {
        xp[b] = (float*)(rnn + (size_t)(b_base + b) * TT * HID + col);
        xv[b] = is_epi ? __ldg(xp[b]) : 0.f;
    }

#pragma unroll 1
    for (int t = 0; t < TT; t++) {
        const int cur = t & 1, nxt = cur ^ 1, par = t & 1;

        // ---- Phase A: arrival (two-in-flight poll on our shared slot word)
        if (!is_epi && t > 0) {
            const float lo = 2.0f * (float)(t & 7);
            const float* src = g_exch + exch_idx(group, cur, kg, j);
            float a0, a1, a2, a3, b0, b1, b2, b3;
            POLL_LD(a0, a1, a2, a3, src);
            for (;;) {
                POLL_LD(b0, b1, b2, b3, src);     // in flight while we check A
                a0 -= lo; a1 -= lo; a2 -= lo; a3 -= lo;
                if (a0 >= 0.f && a0 <= 1.f && a1 >= 0.f && a1 <= 1.f &&
                    a2 >= 0.f && a2 <= 1.f && a3 >= 0.f && a3 <= 1.f) break;
                POLL_LD(a0, a1, a2, a3, src);     // in flight while we check B
                b0 -= lo; b1 -= lo; b2 -= lo; b3 -= lo;
                if (b0 >= 0.f && b0 <= 1.f && b1 >= 0.f && b1 <= 1.f &&
                    b2 >= 0.f && b2 <= 1.f && b3 >= 0.f && b3 <= 1.f) {
                    a0 = b0; a1 = b1; a2 = b2; a3 = b3; break;
                }
            }
            float* hb = &h_perm[cur][kg * 256];
            hb[0 * 64 + j] = a0;
            hb[1 * 64 + j] = a1;
            hb[2 * 64 + j] = a2;
            hb[3 * 64 + j] = a3;
        }
        // group rendezvous: all 64 words of block kg staged
        asm volatile("bar.sync %0, 64;" :: "r"(kg + 1) : "memory");

        // ---- Phase B: FMA over our block for 4 batches ----
        const float* hc = &h_perm[cur][kg * 256];
        const ulonglong2* hp0 = (const ulonglong2*)(hc);
        const ulonglong2* hp1 = (const ulonglong2*)(hc + 64);
        const ulonglong2* hp2 = (const ulonglong2*)(hc + 128);
        const ulonglong2* hp3 = (const ulonglong2*)(hc + 192);
        u64 a0 = 0ull, a1 = 0ull, a2 = 0ull, a3 = 0ull;
#pragma unroll
        for (int q = 0; q < 16; q++) {
            const ulonglong2 v0 = hp0[q];
            a0 = f2fma(v0.x, w2[2 * q], a0); a0 = f2fma(v0.y, w2[2 * q + 1], a0);
            const ulonglong2 v1 = hp1[q];
            a1 = f2fma(v1.x, w2[2 * q], a1); a1 = f2fma(v1.y, w2[2 * q + 1], a1);
            const ulonglong2 v2 = hp2[q];
            a2 = f2fma(v2.x, w2[2 * q], a2); a2 = f2fma(v2.y, w2[2 * q + 1], a2);
            const ulonglong2 v3 = hp3[q];
            a3 = f2fma(v3.x, w2[2 * q], a3); a3 = f2fma(v3.y, w2[2 * q + 1], a3);
        }
        {
            float lo, hi, s0, s1, s2, s3;
            upk(a0, lo, hi); s0 = lo + hi;
            upk(a1, lo, hi); s1 = lo + hi;
            upk(a2, lo, hi); s2 = lo + hi;
            upk(a3, lo, hi); s3 = lo + hi;
            *(float4*)&red4[par][kg][j][0] = make_float4(s0, s1, s2, s3);
        }

        // ---- producer/consumer rendezvous on red4[par] (alternating ids) ----
        if (is_epi) {
            asm volatile("bar.sync %0, %1;" :: "r"(9 + par), "r"(NTHR) : "memory");

            // ---- Phase C: epilogue (epi group only) ----
            float v0 = xv[0], v1 = xv[1], v2 = xv[2], v3 = xv[3];
#pragma unroll
            for (int r = 0; r < GNC; r++) {
                const float4 p = *(const float4*)&red4[par][r][j][0];
                v0 += p.x; v1 += p.y; v2 += p.z; v3 += p.w;
            }
            float h4[NB];
            h4[0] = 1.f / (1.f + __expf(-v0));
            h4[1] = 1.f / (1.f + __expf(-v1));
            h4[2] = 1.f / (1.f + __expf(-v2));
            h4[3] = 1.f / (1.f + __expf(-v3));

            if (t < TT - 1) {
                // SEND FIRST (this is the inter-CTA critical path)
                const float tagf = 2.0f * (float)((t + 1) & 7);
                float* dst = g_exch + exch_idx(group, nxt, rank_i, j);
                asm volatile("st.global.cg.v4.f32 [%0], {%1,%2,%3,%4};"
                             :: "l"(dst),
                                "f"(h4[0] + tagf), "f"(h4[1] + tagf),
                                "f"(h4[2] + tagf), "f"(h4[3] + tagf)
                             : "memory");
                // then local staging for next step
                float* hb = &h_perm[nxt][rank_i * 256];
                hb[0 * 64 + j] = h4[0];
                hb[1 * 64 + j] = h4[1];
                hb[2 * 64 + j] = h4[2];
                hb[3 * 64 + j] = h4[3];
                // off critical path: outputs + next x prefetch
#pragma unroll
                for (int b = 0; b < NB; b++) {
                    xp[b][(size_t)t * HID] = h4[b];
                    xv[b] = __ldg(xp[b] + (size_t)(t + 1) * HID);
                }
            } else {
#pragma unroll
                for (int b = 0; b < NB; b++) {
                    xp[b][(size_t)t * HID] = h4[b];
                    hn_last[(size_t)(b_base + b) * HID + col] = h4[b];
                }
            }
        } else {
            // non-epi: release red4[par] and flow ahead into next step's poll
            asm volatile("bar.arrive %0, %1;" :: "r"(9 + par), "r"(NTHR) : "memory");
        }
    }
}

// ---------------------------------------------------------------------------
// Kernel C: out = sigmoid(rnn_out @ W_fc + b_fc). One warp per (b,t) row.
// ---------------------------------------------------------------------------
__global__ void __launch_bounds__(256, 8) k_fc(
    const float* __restrict__ rnn, const float* __restrict__ W_fc,
    const float* __restrict__ b_fc, float* __restrict__ out)
{
    __shared__ float wfc[HID * NACT];
    for (int i = threadIdx.x; i < HID * NACT; i += 256) wfc[i] = W_fc[i];
    __syncthreads();

    const int warp = threadIdx.x >> 5, lane = threadIdx.x & 31;
    const size_t row = (size_t)blockIdx.x * 8 + warp;
    const float4* rp = reinterpret_cast<const float4*>(rnn + row * HID);

    float a0 = 0.f, a1 = 0.f;
#pragma unroll
    for (int i = 0; i < 4; i++) {
        const float4 vv = rp[lane + 32 * i];
        const int k = (lane + 32 * i) * 4;
        a0 = fmaf(vv.x, wfc[(k + 0) * 2 + 0], a0);
        a1 = fmaf(vv.x, wfc[(k + 0) * 2 + 1], a1);
        a0 = fmaf(vv.y, wfc[(k + 1) * 2 + 0], a0);
        a1 = fmaf(vv.y, wfc[(k + 1) * 2 + 1], a1);
        a0 = fmaf(vv.z, wfc[(k + 2) * 2 + 0], a0);
        a1 = fmaf(vv.z, wfc[(k + 2) * 2 + 1], a1);
        a0 = fmaf(vv.w, wfc[(k + 3) * 2 + 0], a0);
        a1 = fmaf(vv.w, wfc[(k + 3) * 2 + 1], a1);
    }
#pragma unroll
    for (int off = 16; off > 0; off >>= 1) {
        a0 += __shfl_xor_sync(0xffffffffu, a0, off);
        a1 += __shfl_xor_sync(0xffffffffu, a1, off);
    }
    if (lane == 0) {
        out[row * NACT + 0] = 1.f / (1.f + __expf(-(a0 + b_fc[0])));
        out[row * NACT + 1] = 1.f / (1.f + __expf(-(a1 + b_fc[1])));
    }
}

// ---------------------------------------------------------------------------
extern "C" void kernel_launch(void* const* d_in, const int* in_sizes, int n_in,
                              void* d_out, int out_size)
{
    const float* inp  = (const float*)d_in[0];
    const float* hn   = (const float*)d_in[1];
    const float* W_hh = (const float*)d_in[2];
    const float* W_ih = (const float*)d_in[3];
    const float* W_fc = (const float*)d_in[4];
    const float* b_fc = (const float*)d_in[5];

    float* out = (float*)d_out;
    float* hnl = out + HN_OFF;
    float* rnn = out + RNN_OFF;

    k_clear<<<64, 256>>>();                               // reset exchange tags
    k_inproj<<<(BATCH * TT) / 32, 512>>>(inp, W_ih, rnn);
    k_nop<<<1, 32>>>();                                   // ncu index alignment
    k_rnn<<<NGROUP * GNC, NTHR>>>(hn, W_hh, rnn, hnl);
    k_fc<<<(BATCH * TT) / 8, 256>>>(rnn, W_fc, b_fc, out);
}